// round 16
// baseline (speedup 1.0000x reference)
#include <cuda_runtime.h>
#include <cuda_bf16.h>
#include <cooperative_groups.h>
#include <cstdint>
namespace cg = cooperative_groups;

#define D      512
#define NWAY   64
#define KSHOT  16
#define MAXQ   8192
#define SA     72            // smem K-stride (bf16): 144B rows, LDSM conflict-free
#define PA     (64 * SA)
#define PB     (128 * SA)
#define ASZ    (128 * SA)
#define BSZ    (64 * SA)

// ---------------- device scratch ----------------
__device__ __nv_bfloat16  g_smeanbf[NWAY * D];
__device__ __nv_bfloat16  g_Pbf[NWAY * D];
__device__ float          g_Ppart[8 * NWAY * D];
__device__ float          g_Rpart[8 * NWAY * D];
__device__ float          g_pcterm[NWAY];
__device__ __nv_bfloat16  g_qbf[(size_t)MAXQ * D];
__device__ __nv_bfloat16  g_Bbig[(512 + NWAY) * D];  // 0..511 W(bf16), 512..575 R
__device__ __nv_bfloat16  g_WbfT[D * D];             // WbfT[k, j] = W[j, k]
__device__ float          g_partial[(size_t)MAXQ * 8];
__device__ float          g_cross[(size_t)MAXQ * NWAY];

// ---------------- mma / ldmatrix / cp.async helpers ----------------
__device__ __forceinline__ void mma16816(float* c,
                                         uint32_t a0, uint32_t a1, uint32_t a2, uint32_t a3,
                                         uint32_t b0, uint32_t b1) {
    asm volatile(
        "mma.sync.aligned.m16n8k16.row.col.f32.bf16.bf16.f32 "
        "{%0,%1,%2,%3},{%4,%5,%6,%7},{%8,%9},{%0,%1,%2,%3};\n"
        : "+f"(c[0]), "+f"(c[1]), "+f"(c[2]), "+f"(c[3])
        : "r"(a0), "r"(a1), "r"(a2), "r"(a3), "r"(b0), "r"(b1));
}
__device__ __forceinline__ void ldsm4(uint32_t* r, uint32_t a) {
    asm volatile("ldmatrix.sync.aligned.m8n8.x4.shared.b16 {%0,%1,%2,%3}, [%4];"
                 : "=r"(r[0]), "=r"(r[1]), "=r"(r[2]), "=r"(r[3]) : "r"(a));
}
__device__ __forceinline__ void cp_async16(void* smem, const void* gmem) {
    uint32_t s = (uint32_t)__cvta_generic_to_shared(smem);
    asm volatile("cp.async.cg.shared.global [%0], [%1], 16;\n" :: "r"(s), "l"(gmem));
}
#define CP_COMMIT() asm volatile("cp.async.commit_group;\n")
#define CP_WAIT(n)  asm volatile("cp.async.wait_group %0;\n" :: "n"(n))

// One K=64 slab, 64Mx128N CTA, warp 32x32, 2x4 frags.
__device__ __forceinline__ void tile_step_small(float acc[2][4][4], uint32_t aA, uint32_t aB,
                                                int aOff0, int aOff1, int bOff0, int bOff1) {
    #pragma unroll
    for (int kk = 0; kk < 64; kk += 16) {
        uint32_t br0[4], br1[4];
        ldsm4(br0, aB + bOff0 + kk * 2);
        ldsm4(br1, aB + bOff1 + kk * 2);
        #pragma unroll
        for (int mf = 0; mf < 2; mf++) {
            uint32_t ar[4];
            ldsm4(ar, aA + (mf ? aOff1 : aOff0) + kk * 2);
            mma16816(acc[mf][0], ar[0], ar[1], ar[2], ar[3], br0[0], br0[1]);
            mma16816(acc[mf][1], ar[0], ar[1], ar[2], ar[3], br0[2], br0[3]);
            mma16816(acc[mf][2], ar[0], ar[1], ar[2], ar[3], br1[0], br1[1]);
            mma16816(acc[mf][3], ar[0], ar[1], ar[2], ar[3], br1[2], br1[3]);
        }
    }
}

// ================= shared phase bodies (used by coop kernel AND fallback kernels) =================

// 64x128 GEMM tile, single K=64 chunk: C(part) = A[64xD] @ B[128xD]^T over k-chunk ks
__device__ void small_gemm_body(char* sm_c, const __nv_bfloat16* Asrc, const __nv_bfloat16* Bsrc,
                                float* Cdst, int n0, int ks, int tid) {
    __nv_bfloat16* sA = (__nv_bfloat16*)sm_c;
    __nv_bfloat16* sB = sA + PA;
    int warp = tid >> 5, lane = tid & 31;
    int wm = warp & 1, wn = warp >> 1;
    int g = lane >> 2, t4 = lane & 3;

    int aOff0 = (((wm * 32 + 0 + (lane & 15)) * SA + (lane >> 4) * 8)) * 2;
    int aOff1 = (((wm * 32 + 16 + (lane & 15)) * SA + (lane >> 4) * 8)) * 2;
    int bOff0 = (((wn * 32 + 0 + (lane & 7) + ((lane >> 4) << 3)) * SA + ((lane >> 3) & 1) * 8)) * 2;
    int bOff1 = (((wn * 32 + 16 + (lane & 7) + ((lane >> 4) << 3)) * SA + ((lane >> 3) & 1) * 8)) * 2;

    #pragma unroll
    for (int j = 0; j < 2; j++) {
        int i = tid + j * 256, r = i >> 3, c8 = i & 7;
        cp_async16(sA + r * SA + c8 * 8, Asrc + (size_t)r * D + ks * 64 + c8 * 8);
    }
    #pragma unroll
    for (int j = 0; j < 4; j++) {
        int i = tid + j * 256, r = i >> 3, c8 = i & 7;
        cp_async16(sB + r * SA + c8 * 8, Bsrc + (size_t)(n0 + r) * D + ks * 64 + c8 * 8);
    }
    CP_COMMIT();

    float acc[2][4][4];
    #pragma unroll
    for (int a = 0; a < 2; a++)
        #pragma unroll
        for (int b2 = 0; b2 < 4; b2++)
            #pragma unroll
            for (int c = 0; c < 4; c++) acc[a][b2][c] = 0.f;

    CP_WAIT(0); __syncthreads();
    tile_step_small(acc, (uint32_t)__cvta_generic_to_shared(sA),
                    (uint32_t)__cvta_generic_to_shared(sB), aOff0, aOff1, bOff0, bOff1);

    #pragma unroll
    for (int mf = 0; mf < 2; mf++) {
        int m = wm * 32 + mf * 16 + g;
        #pragma unroll
        for (int nf = 0; nf < 4; nf++) {
            int c = n0 + wn * 32 + nf * 8 + t4 * 2;
            float2 o0; o0.x = acc[mf][nf][0]; o0.y = acc[mf][nf][1];
            float2 o1; o1.x = acc[mf][nf][2]; o1.y = acc[mf][nf][3];
            *(float2*)(Cdst + (size_t)m * D + c) = o0;
            *(float2*)(Cdst + (size_t)(m + 8) * D + c) = o1;
        }
    }
    __syncthreads();   // smem reusable by caller afterwards
}

// pred for one class: P = sum(8 Ppart) + b -> Pbf; pcterm[c] (256 threads)
__device__ void pred_body(const float* bias, int c, int tid) {
    __shared__ float red[8];
    float pc = 0.f;
    #pragma unroll
    for (int h = 0; h < 2; h++) {
        int j = tid + h * 256;
        float bj = bias[j];
        float v = bj;
        #pragma unroll
        for (int kp = 0; kp < 8; kp++)
            v += g_Ppart[(size_t)kp * NWAY * D + (size_t)c * D + j];
        g_Pbf[c * D + j] = __float2bfloat16(v);
        pc += v * (v - 2.f * bj);
    }
    #pragma unroll
    for (int o = 16; o > 0; o >>= 1) pc += __shfl_xor_sync(0xffffffffu, pc, o);
    if ((tid & 31) == 0) red[tid >> 5] = pc;
    __syncthreads();
    if (tid == 0) {
        float t2 = 0.f;
        #pragma unroll
        for (int w = 0; w < 8; w++) t2 += red[w];
        g_pcterm[c] = t2;
    }
    __syncthreads();
}

// W transpose: one 64x64 tile (256 threads), smem = float[64][68]
__device__ void wt_tile_body(char* sm_c, const float* W, int t, int tid) {
    float (*ts)[68] = (float(*)[68])sm_c;
    int r0 = (t >> 3) * 64, c0 = (t & 7) * 64;
    __syncthreads();
    #pragma unroll
    for (int it = 0; it < 4; it++) {
        int r = (tid >> 4) + it * 16;
        float4 v = *(const float4*)(W + (size_t)(r0 + r) * D + c0 + (tid & 15) * 4);
        ts[r][(tid & 15) * 4 + 0] = v.x; ts[r][(tid & 15) * 4 + 1] = v.y;
        ts[r][(tid & 15) * 4 + 2] = v.z; ts[r][(tid & 15) * 4 + 3] = v.w;
    }
    __syncthreads();
    int kk = tid >> 2, jb = (tid & 3) * 16;
    #pragma unroll
    for (int e = 0; e < 16; e += 2) {
        *(__nv_bfloat162*)(g_WbfT + (size_t)(c0 + kk) * D + r0 + jb + e) =
            __floats2bfloat162_rn(ts[jb + e][kk], ts[jb + e + 1][kk]);
    }
}

// ================= kernels =================

__global__ void prep_q_kernel(const float* __restrict__ q, int M) {
    size_t total = (size_t)M * D;
    size_t base = (size_t)blockIdx.x * 2048 + threadIdx.x * 8;
    if (base + 8 <= total) {
        float4 v0 = *(const float4*)(q + base);
        float4 v1 = *(const float4*)(q + base + 4);
        __nv_bfloat162 p0 = __floats2bfloat162_rn(v0.x, v0.y);
        __nv_bfloat162 p1 = __floats2bfloat162_rn(v0.z, v0.w);
        __nv_bfloat162 p2 = __floats2bfloat162_rn(v1.x, v1.y);
        __nv_bfloat162 p3 = __floats2bfloat162_rn(v1.z, v1.w);
        uint4 o;
        o.x = *(uint32_t*)&p0; o.y = *(uint32_t*)&p1;
        o.z = *(uint32_t*)&p2; o.w = *(uint32_t*)&p3;
        *(uint4*)(g_qbf + base) = o;
    } else {
        for (int e = 0; e < 8; e++)
            if (base + e < total) g_qbf[base + e] = __float2bfloat16(q[base + e]);
    }
}

// ---------------- ONE cooperative kernel for the whole prototype chain ----------------
// 32 blocks x 256 threads; phases split by grid.sync().
#define SM_COOP 28672

__global__ __launch_bounds__(256) void proto_coop(const float* __restrict__ W,
                                                  const float* __restrict__ support,
                                                  const float* __restrict__ bias) {
    cg::grid_group grid = cg::this_grid();
    extern __shared__ char smc[];
    int b = blockIdx.x, tid = threadIdx.x;
    int gtid = b * 256 + tid;

    // phase 0a: W -> bf16 into Bbig rows 0..511
    #pragma unroll 1
    for (int i = gtid * 4; i < D * D; i += 32 * 256 * 4) {
        float4 v = *(const float4*)(W + i);
        *(__nv_bfloat162*)(g_Bbig + i)     = __floats2bfloat162_rn(v.x, v.y);
        *(__nv_bfloat162*)(g_Bbig + i + 2) = __floats2bfloat162_rn(v.z, v.w);
    }
    // phase 0b: class means (2 per block)
    #pragma unroll
    for (int cc = 0; cc < 2; cc++) {
        int c = b * 2 + cc;
        for (int col = tid; col < D; col += 256) {
            float s = 0.f;
            #pragma unroll
            for (int k = 0; k < KSHOT; k++) s += support[(size_t)(c * KSHOT + k) * D + col];
            g_smeanbf[c * D + col] = __float2bfloat16(s * (1.f / KSHOT));
        }
    }
    // phase 0c: W^T (2 tiles per block)
    wt_tile_body(smc, W, b * 2, tid);
    wt_tile_body(smc, W, b * 2 + 1, tid);

    grid.sync();

    // phase 1: proj — Ppart[ks] tile: n0 = (b&3)*128, ks = b>>2
    small_gemm_body(smc, g_smeanbf, g_Bbig, g_Ppart + (size_t)(b >> 2) * NWAY * D,
                    (b & 3) * 128, b >> 2, tid);

    grid.sync();

    // phase 2: pred (2 classes per block)
    pred_body(bias, b * 2, tid);
    pred_body(bias, b * 2 + 1, tid);

    grid.sync();

    // phase 3: r2 — Rpart[js] tile: n0 = (b&3)*128, js = b>>2
    small_gemm_body(smc, g_Pbf, g_WbfT, g_Rpart + (size_t)(b >> 2) * NWAY * D,
                    (b & 3) * 128, b >> 2, tid);

    grid.sync();

    // phase 4: rred — R = sum(8 Rpart) -> Bbig rows 512..575
    #pragma unroll 1
    for (int i = gtid; i < NWAY * D; i += 32 * 256) {
        int c = i >> 9, k = i & (D - 1);
        float v = 0.f;
        #pragma unroll
        for (int js = 0; js < 8; js++)
            v += g_Rpart[(size_t)js * NWAY * D + (size_t)c * D + k];
        g_Bbig[(size_t)(512 + c) * D + k] = __float2bfloat16(v);
    }
}

// ---------------- fallback standalone kernels (if cooperative launch unavailable) ----------------
__global__ void prep_w_kernel(const float* __restrict__ W, const float* __restrict__ support) {
    __shared__ char smc[64 * 68 * 4];
    int b = blockIdx.x, tid = threadIdx.x;
    if (b < 256) {
        int base = b * 1024 + tid * 4;
        float4 v = *(const float4*)(W + base);
        *(__nv_bfloat162*)(g_Bbig + base)     = __floats2bfloat162_rn(v.x, v.y);
        *(__nv_bfloat162*)(g_Bbig + base + 2) = __floats2bfloat162_rn(v.z, v.w);
    } else if (b < 256 + 64) {
        wt_tile_body(smc, W, b - 256, tid);
    } else {
        int c = b - 256 - 64;
        for (int col = tid; col < D; col += blockDim.x) {
            float s = 0.f;
            #pragma unroll
            for (int k = 0; k < KSHOT; k++) s += support[(size_t)(c * KSHOT + k) * D + col];
            g_smeanbf[c * D + col] = __float2bfloat16(s * (1.f / KSHOT));
        }
    }
}
__global__ __launch_bounds__(256) void proj_gemm(int dummy) {
    extern __shared__ char smc[];
    small_gemm_body(smc, g_smeanbf, g_Bbig, g_Ppart + (size_t)blockIdx.y * NWAY * D,
                    blockIdx.x * 128, blockIdx.y, threadIdx.x);
}
__global__ void pred_kernel(const float* __restrict__ bias) {
    pred_body(bias, blockIdx.x, threadIdx.x);
}
__global__ __launch_bounds__(256) void r2_gemm(int dummy) {
    extern __shared__ char smc[];
    small_gemm_body(smc, g_Pbf, g_WbfT, g_Rpart + (size_t)blockIdx.y * NWAY * D,
                    blockIdx.x * 128, blockIdx.y, threadIdx.x);
}
__global__ void rred_kernel(int dummy) {
    int c = blockIdx.x;
    int k = blockIdx.y * 128 + threadIdx.x;
    float v = 0.f;
    #pragma unroll
    for (int js = 0; js < 8; js++)
        v += g_Rpart[(size_t)js * NWAY * D + (size_t)c * D + k];
    g_Bbig[(size_t)(512 + c) * D + k] = __float2bfloat16(v);
}

// ---------------- main GEMM: round-10 config (CTA 128x64, 4-stage, grid (M/128, 9)) ----------------
#define SM_BIAS  (4 * (ASZ + BSZ) * 2)
#define SM_NORM  (SM_BIAS + 64 * 4)
#define SM_MAIN  (SM_NORM + 128 * 2 * 4)

__global__ __launch_bounds__(256, 2) void main_gemm(const float* __restrict__ bias, int M) {
    extern __shared__ char smc[];
    __nv_bfloat16* sA = (__nv_bfloat16*)smc;
    __nv_bfloat16* sB = (__nv_bfloat16*)smc + 4 * ASZ;
    float* sbias = (float*)(smc + SM_BIAS);
    float* snorm = (float*)(smc + SM_NORM);

    int tid = threadIdx.x;
    int m0 = blockIdx.x * 128;
    int nt = blockIdx.y;
    int n0 = nt * 64;
    int warp = tid >> 5, lane = tid & 31;
    int wm = warp & 3, wn = warp >> 2;
    int g = lane >> 2, t4 = lane & 3;

    if (nt < 8 && tid < 64) sbias[tid] = bias[n0 + tid];

    int aOff0 = (((wm * 32 + 0 + (lane & 15)) * SA + (lane >> 4) * 8)) * 2;
    int aOff1 = (((wm * 32 + 16 + (lane & 15)) * SA + (lane >> 4) * 8)) * 2;
    int bOff0 = (((wn * 32 + 0 + (lane & 7) + ((lane >> 4) << 3)) * SA + ((lane >> 3) & 1) * 8)) * 2;
    int bOff1 = (((wn * 32 + 16 + (lane & 7) + ((lane >> 4) << 3)) * SA + ((lane >> 3) & 1) * 8)) * 2;

    float acc[2][4][4];
    #pragma unroll
    for (int a = 0; a < 2; a++)
        #pragma unroll
        for (int b2 = 0; b2 < 4; b2++)
            #pragma unroll
            for (int c = 0; c < 4; c++) acc[a][b2][c] = 0.f;

    auto loadA = [&](int st, int kt) {
        #pragma unroll
        for (int j = 0; j < 4; j++) {
            int i = tid + j * 256, r = i >> 3, c8 = i & 7;
            int grow = m0 + r; if (grow >= M) grow = M - 1;
            cp_async16(sA + st * ASZ + r * SA + c8 * 8,
                       g_qbf + (size_t)grow * D + kt * 64 + c8 * 8);
        }
    };
    auto loadB = [&](int st, int kt) {
        #pragma unroll
        for (int j = 0; j < 2; j++) {
            int i = tid + j * 256, r = i >> 3, c8 = i & 7;
            cp_async16(sB + st * BSZ + r * SA + c8 * 8,
                       g_Bbig + (size_t)(n0 + r) * D + kt * 64 + c8 * 8);
        }
    };

    loadA(0, 0); loadB(0, 0); CP_COMMIT();
    loadA(1, 1); loadB(1, 1); CP_COMMIT();
    loadA(2, 2); loadB(2, 2); CP_COMMIT();

    uint32_t sa0 = (uint32_t)__cvta_generic_to_shared(sA);
    uint32_t sb0 = (uint32_t)__cvta_generic_to_shared(sB);

    #pragma unroll 1
    for (int kt = 0; kt < 8; kt++) {
        if (kt < 6) { CP_WAIT(2); } else if (kt == 6) { CP_WAIT(1); } else { CP_WAIT(0); }
        __syncthreads();
        if (kt + 3 < 8) { loadA((kt + 3) & 3, kt + 3); loadB((kt + 3) & 3, kt + 3); CP_COMMIT(); }
        tile_step_small(acc, sa0 + ((kt & 3) * ASZ) * 2, sb0 + ((kt & 3) * BSZ) * 2,
                        aOff0, aOff1, bOff0, bOff1);
        __syncthreads();
    }

    if (nt < 8) {
        #pragma unroll
        for (int mf = 0; mf < 2; mf++) {
            float s0 = 0.f, s1 = 0.f;
            #pragma unroll
            for (int nf = 0; nf < 4; nf++) {
                int c = wn * 32 + nf * 8 + t4 * 2;
                float b0 = sbias[c], b1 = sbias[c + 1];
                float v;
                v = acc[mf][nf][0] + b0; s0 += v * v;
                v = acc[mf][nf][1] + b1; s0 += v * v;
                v = acc[mf][nf][2] + b0; s1 += v * v;
                v = acc[mf][nf][3] + b1; s1 += v * v;
            }
            s0 += __shfl_xor_sync(0xffffffffu, s0, 1);
            s0 += __shfl_xor_sync(0xffffffffu, s0, 2);
            s1 += __shfl_xor_sync(0xffffffffu, s1, 1);
            s1 += __shfl_xor_sync(0xffffffffu, s1, 2);
            if (t4 == 0) {
                int r = wm * 32 + mf * 16 + g;
                snorm[r * 2 + wn] = s0;
                snorm[(r + 8) * 2 + wn] = s1;
            }
        }
        __syncthreads();
        if (tid < 128 && m0 + tid < M)
            g_partial[(size_t)(m0 + tid) * 8 + nt] = snorm[tid * 2] + snorm[tid * 2 + 1];
    } else {
        #pragma unroll
        for (int mf = 0; mf < 2; mf++) {
            int r = wm * 32 + mf * 16 + g;
            #pragma unroll
            for (int nf = 0; nf < 4; nf++) {
                int c = wn * 32 + nf * 8 + t4 * 2;
                if (m0 + r < M) {
                    float2 o; o.x = acc[mf][nf][0]; o.y = acc[mf][nf][1];
                    *(float2*)(g_cross + (size_t)(m0 + r) * NWAY + c) = o;
                }
                if (m0 + r + 8 < M) {
                    float2 o; o.x = acc[mf][nf][2]; o.y = acc[mf][nf][3];
                    *(float2*)(g_cross + (size_t)(m0 + r + 8) * NWAY + c) = o;
                }
            }
        }
    }
}

// ---------------- combine: dist = nq + pcterm - 2*cross ----------------
__global__ void combine_kernel(float* __restrict__ out, int M) {
    __shared__ float snq[4];
    int tid = threadIdx.x;
    int q0 = blockIdx.x * 4;
    if (tid < 4 && q0 + tid < M) {
        float s = 0.f;
        #pragma unroll
        for (int t = 0; t < 8; t++) s += g_partial[(size_t)(q0 + tid) * 8 + t];
        snq[tid] = s;
    }
    __syncthreads();
    int q = q0 + (tid >> 6), c = tid & 63;
    if (q < M)
        out[(size_t)q * NWAY + c] = snq[tid >> 6] + g_pcterm[c]
                                    - 2.f * g_cross[(size_t)q * NWAY + c];
}

// ---------------- launch ----------------
extern "C" void kernel_launch(void* const* d_in, const int* in_sizes, int n_in,
                              void* d_out, int out_size) {
    const float* support = (const float*)d_in[0];
    const float* query   = (const float*)d_in[1];
    const float* W       = (const float*)d_in[2];
    const float* bias    = (const float*)d_in[3];
    int M = in_sizes[1] / D;
    if (M > MAXQ) M = MAXQ;
    float* out = (float*)d_out;
    int qblocks = (int)(((size_t)M * D + 2047) / 2048);
    int mblocks = (M + 127) / 128;

    cudaFuncSetAttribute(main_gemm, cudaFuncAttributeMaxDynamicSharedMemorySize, SM_MAIN);

    int coopOK = 0;
    cudaDeviceGetAttribute(&coopOK, cudaDevAttrCooperativeLaunch, 0);

    prep_q_kernel<<<qblocks, 256>>>(query, M);

    bool launched = false;
    if (coopOK) {
        void* args[3] = { (void*)&W, (void*)&support, (void*)&bias };
        cudaError_t e = cudaLaunchCooperativeKernel((const void*)proto_coop,
                                                    dim3(32), dim3(256), args, SM_COOP,
                                                    (cudaStream_t)0);
        launched = (e == cudaSuccess);
    }
    if (!launched) {
        prep_w_kernel<<<256 + 64 + 64, 256>>>(W, support);
        proj_gemm<<<dim3(4, 8), 256, SM_COOP>>>(0);
        pred_kernel<<<NWAY, 256>>>(bias);
        r2_gemm<<<dim3(4, 8), 256, SM_COOP>>>(0);
        rred_kernel<<<dim3(NWAY, 4), 128>>>(0);
    }

    main_gemm<<<dim3(mblocks, 9), 256, SM_MAIN>>>(bias, M);
    combine_kernel<<<(M + 3) / 4, 256>>>(out, M);
}

// round 17
// speedup vs baseline: 1.0034x; 1.0034x over previous
#include <cuda_runtime.h>
#include <cuda_bf16.h>
#include <cooperative_groups.h>
#include <cstdint>
namespace cg = cooperative_groups;

#define D      512
#define NWAY   64
#define KSHOT  16
#define MAXQ   8192
#define SA     72            // smem K-stride (bf16): 144B rows, LDSM conflict-free
#define PA     (64 * SA)
#define PB     (128 * SA)
#define ASZ    (128 * SA)
#define BSZ    (64 * SA)

// ---------------- device scratch ----------------
__device__ __nv_bfloat16  g_smeanbf[NWAY * D];
__device__ __nv_bfloat16  g_Pbf[NWAY * D];
__device__ float          g_Ppart[8 * NWAY * D];
__device__ float          g_Rpart[8 * NWAY * D];
__device__ float          g_pcterm[NWAY];
__device__ __nv_bfloat16  g_qbf[(size_t)MAXQ * D];
__device__ __nv_bfloat16  g_Bbig[(512 + NWAY) * D];  // 0..511 W(bf16), 512..575 R
__device__ __nv_bfloat16  g_WbfT[D * D];             // WbfT[k, j] = W[j, k]
__device__ float          g_partial[(size_t)MAXQ * 8];
__device__ float          g_cross[(size_t)MAXQ * NWAY];

// ---------------- mma / ldmatrix / cp.async helpers ----------------
__device__ __forceinline__ void mma16816(float* c,
                                         uint32_t a0, uint32_t a1, uint32_t a2, uint32_t a3,
                                         uint32_t b0, uint32_t b1) {
    asm volatile(
        "mma.sync.aligned.m16n8k16.row.col.f32.bf16.bf16.f32 "
        "{%0,%1,%2,%3},{%4,%5,%6,%7},{%8,%9},{%0,%1,%2,%3};\n"
        : "+f"(c[0]), "+f"(c[1]), "+f"(c[2]), "+f"(c[3])
        : "r"(a0), "r"(a1), "r"(a2), "r"(a3), "r"(b0), "r"(b1));
}
__device__ __forceinline__ void ldsm4(uint32_t* r, uint32_t a) {
    asm volatile("ldmatrix.sync.aligned.m8n8.x4.shared.b16 {%0,%1,%2,%3}, [%4];"
                 : "=r"(r[0]), "=r"(r[1]), "=r"(r[2]), "=r"(r[3]) : "r"(a));
}
__device__ __forceinline__ void cp_async16(void* smem, const void* gmem) {
    uint32_t s = (uint32_t)__cvta_generic_to_shared(smem);
    asm volatile("cp.async.cg.shared.global [%0], [%1], 16;\n" :: "r"(s), "l"(gmem));
}
#define CP_COMMIT() asm volatile("cp.async.commit_group;\n")
#define CP_WAIT(n)  asm volatile("cp.async.wait_group %0;\n" :: "n"(n))

// One K=64 slab, warp 32x32-ish, 2x4 frags. NO trailing barrier (caller controls).
__device__ __forceinline__ void tile_step_small(float acc[2][4][4], uint32_t aA, uint32_t aB,
                                                int aOff0, int aOff1, int bOff0, int bOff1) {
    #pragma unroll
    for (int kk = 0; kk < 64; kk += 16) {
        uint32_t br0[4], br1[4];
        ldsm4(br0, aB + bOff0 + kk * 2);
        ldsm4(br1, aB + bOff1 + kk * 2);
        #pragma unroll
        for (int mf = 0; mf < 2; mf++) {
            uint32_t ar[4];
            ldsm4(ar, aA + (mf ? aOff1 : aOff0) + kk * 2);
            mma16816(acc[mf][0], ar[0], ar[1], ar[2], ar[3], br0[0], br0[1]);
            mma16816(acc[mf][1], ar[0], ar[1], ar[2], ar[3], br0[2], br0[3]);
            mma16816(acc[mf][2], ar[0], ar[1], ar[2], ar[3], br1[0], br1[1]);
            mma16816(acc[mf][3], ar[0], ar[1], ar[2], ar[3], br1[2], br1[3]);
        }
    }
}

// ================= shared phase bodies =================

// 64x128 GEMM tile, single K=64 chunk: Cpart = A[64xD] @ B[128xD]^T over chunk ks
__device__ void small_gemm_body(char* sm_c, const __nv_bfloat16* Asrc, const __nv_bfloat16* Bsrc,
                                float* Cdst, int n0, int ks, int tid) {
    __nv_bfloat16* sA = (__nv_bfloat16*)sm_c;
    __nv_bfloat16* sB = sA + PA;
    int warp = tid >> 5, lane = tid & 31;
    int wm = warp & 1, wn = warp >> 1;
    int g = lane >> 2, t4 = lane & 3;

    int aOff0 = (((wm * 32 + 0 + (lane & 15)) * SA + (lane >> 4) * 8)) * 2;
    int aOff1 = (((wm * 32 + 16 + (lane & 15)) * SA + (lane >> 4) * 8)) * 2;
    int bOff0 = (((wn * 32 + 0 + (lane & 7) + ((lane >> 4) << 3)) * SA + ((lane >> 3) & 1) * 8)) * 2;
    int bOff1 = (((wn * 32 + 16 + (lane & 7) + ((lane >> 4) << 3)) * SA + ((lane >> 3) & 1) * 8)) * 2;

    #pragma unroll
    for (int j = 0; j < 2; j++) {
        int i = tid + j * 256, r = i >> 3, c8 = i & 7;
        cp_async16(sA + r * SA + c8 * 8, Asrc + (size_t)r * D + ks * 64 + c8 * 8);
    }
    #pragma unroll
    for (int j = 0; j < 4; j++) {
        int i = tid + j * 256, r = i >> 3, c8 = i & 7;
        cp_async16(sB + r * SA + c8 * 8, Bsrc + (size_t)(n0 + r) * D + ks * 64 + c8 * 8);
    }
    CP_COMMIT();

    float acc[2][4][4];
    #pragma unroll
    for (int a = 0; a < 2; a++)
        #pragma unroll
        for (int b2 = 0; b2 < 4; b2++)
            #pragma unroll
            for (int c = 0; c < 4; c++) acc[a][b2][c] = 0.f;

    CP_WAIT(0); __syncthreads();
    tile_step_small(acc, (uint32_t)__cvta_generic_to_shared(sA),
                    (uint32_t)__cvta_generic_to_shared(sB), aOff0, aOff1, bOff0, bOff1);

    #pragma unroll
    for (int mf = 0; mf < 2; mf++) {
        int m = wm * 32 + mf * 16 + g;
        #pragma unroll
        for (int nf = 0; nf < 4; nf++) {
            int c = n0 + wn * 32 + nf * 8 + t4 * 2;
            float2 o0; o0.x = acc[mf][nf][0]; o0.y = acc[mf][nf][1];
            float2 o1; o1.x = acc[mf][nf][2]; o1.y = acc[mf][nf][3];
            *(float2*)(Cdst + (size_t)m * D + c) = o0;
            *(float2*)(Cdst + (size_t)(m + 8) * D + c) = o1;
        }
    }
    __syncthreads();
}

__device__ void pred_body(const float* bias, int c, int tid) {
    __shared__ float red[8];
    float pc = 0.f;
    #pragma unroll
    for (int h = 0; h < 2; h++) {
        int j = tid + h * 256;
        float bj = bias[j];
        float v = bj;
        #pragma unroll
        for (int kp = 0; kp < 8; kp++)
            v += g_Ppart[(size_t)kp * NWAY * D + (size_t)c * D + j];
        g_Pbf[c * D + j] = __float2bfloat16(v);
        pc += v * (v - 2.f * bj);
    }
    #pragma unroll
    for (int o = 16; o > 0; o >>= 1) pc += __shfl_xor_sync(0xffffffffu, pc, o);
    if ((tid & 31) == 0) red[tid >> 5] = pc;
    __syncthreads();
    if (tid == 0) {
        float t2 = 0.f;
        #pragma unroll
        for (int w = 0; w < 8; w++) t2 += red[w];
        g_pcterm[c] = t2;
    }
    __syncthreads();
}

__device__ void wt_tile_body(char* sm_c, const float* W, int t, int tid) {
    float (*ts)[68] = (float(*)[68])sm_c;
    int r0 = (t >> 3) * 64, c0 = (t & 7) * 64;
    __syncthreads();
    #pragma unroll
    for (int it = 0; it < 4; it++) {
        int r = (tid >> 4) + it * 16;
        float4 v = *(const float4*)(W + (size_t)(r0 + r) * D + c0 + (tid & 15) * 4);
        ts[r][(tid & 15) * 4 + 0] = v.x; ts[r][(tid & 15) * 4 + 1] = v.y;
        ts[r][(tid & 15) * 4 + 2] = v.z; ts[r][(tid & 15) * 4 + 3] = v.w;
    }
    __syncthreads();
    int kk = tid >> 2, jb = (tid & 3) * 16;
    #pragma unroll
    for (int e = 0; e < 16; e += 2) {
        *(__nv_bfloat162*)(g_WbfT + (size_t)(c0 + kk) * D + r0 + jb + e) =
            __floats2bfloat162_rn(ts[jb + e][kk], ts[jb + e + 1][kk]);
    }
}

// ================= kernels =================

__global__ void prep_q_kernel(const float* __restrict__ q, int M) {
    size_t total = (size_t)M * D;
    size_t base = (size_t)blockIdx.x * 2048 + threadIdx.x * 8;
    if (base + 8 <= total) {
        float4 v0 = *(const float4*)(q + base);
        float4 v1 = *(const float4*)(q + base + 4);
        __nv_bfloat162 p0 = __floats2bfloat162_rn(v0.x, v0.y);
        __nv_bfloat162 p1 = __floats2bfloat162_rn(v0.z, v0.w);
        __nv_bfloat162 p2 = __floats2bfloat162_rn(v1.x, v1.y);
        __nv_bfloat162 p3 = __floats2bfloat162_rn(v1.z, v1.w);
        uint4 o;
        o.x = *(uint32_t*)&p0; o.y = *(uint32_t*)&p1;
        o.z = *(uint32_t*)&p2; o.w = *(uint32_t*)&p3;
        *(uint4*)(g_qbf + base) = o;
    } else {
        for (int e = 0; e < 8; e++)
            if (base + e < total) g_qbf[base + e] = __float2bfloat16(q[base + e]);
    }
}

// ---------------- cooperative prototype chain (32 blocks x 256 thr) ----------------
#define SM_COOP 28672

__global__ __launch_bounds__(256) void proto_coop(const float* __restrict__ W,
                                                  const float* __restrict__ support,
                                                  const float* __restrict__ bias) {
    cg::grid_group grid = cg::this_grid();
    extern __shared__ char smc[];
    int b = blockIdx.x, tid = threadIdx.x;
    int gtid = b * 256 + tid;

    #pragma unroll 1
    for (int i = gtid * 4; i < D * D; i += 32 * 256 * 4) {
        float4 v = *(const float4*)(W + i);
        *(__nv_bfloat162*)(g_Bbig + i)     = __floats2bfloat162_rn(v.x, v.y);
        *(__nv_bfloat162*)(g_Bbig + i + 2) = __floats2bfloat162_rn(v.z, v.w);
    }
    #pragma unroll
    for (int cc = 0; cc < 2; cc++) {
        int c = b * 2 + cc;
        for (int col = tid; col < D; col += 256) {
            float s = 0.f;
            #pragma unroll
            for (int k = 0; k < KSHOT; k++) s += support[(size_t)(c * KSHOT + k) * D + col];
            g_smeanbf[c * D + col] = __float2bfloat16(s * (1.f / KSHOT));
        }
    }
    wt_tile_body(smc, W, b * 2, tid);
    wt_tile_body(smc, W, b * 2 + 1, tid);

    grid.sync();
    small_gemm_body(smc, g_smeanbf, g_Bbig, g_Ppart + (size_t)(b >> 2) * NWAY * D,
                    (b & 3) * 128, b >> 2, tid);
    grid.sync();
    pred_body(bias, b * 2, tid);
    pred_body(bias, b * 2 + 1, tid);
    grid.sync();
    small_gemm_body(smc, g_Pbf, g_WbfT, g_Rpart + (size_t)(b >> 2) * NWAY * D,
                    (b & 3) * 128, b >> 2, tid);
    grid.sync();
    #pragma unroll 1
    for (int i = gtid; i < NWAY * D; i += 32 * 256) {
        int c = i >> 9, k = i & (D - 1);
        float v = 0.f;
        #pragma unroll
        for (int js = 0; js < 8; js++)
            v += g_Rpart[(size_t)js * NWAY * D + (size_t)c * D + k];
        g_Bbig[(size_t)(512 + c) * D + k] = __float2bfloat16(v);
    }
}

// ---------------- fallback standalone kernels ----------------
__global__ void prep_w_kernel(const float* __restrict__ W, const float* __restrict__ support) {
    __shared__ char smc[64 * 68 * 4];
    int b = blockIdx.x, tid = threadIdx.x;
    if (b < 256) {
        int base = b * 1024 + tid * 4;
        float4 v = *(const float4*)(W + base);
        *(__nv_bfloat162*)(g_Bbig + base)     = __floats2bfloat162_rn(v.x, v.y);
        *(__nv_bfloat162*)(g_Bbig + base + 2) = __floats2bfloat162_rn(v.z, v.w);
    } else if (b < 256 + 64) {
        wt_tile_body(smc, W, b - 256, tid);
    } else {
        int c = b - 256 - 64;
        for (int col = tid; col < D; col += blockDim.x) {
            float s = 0.f;
            #pragma unroll
            for (int k = 0; k < KSHOT; k++) s += support[(size_t)(c * KSHOT + k) * D + col];
            g_smeanbf[c * D + col] = __float2bfloat16(s * (1.f / KSHOT));
        }
    }
}
__global__ __launch_bounds__(256) void proj_gemm(int dummy) {
    extern __shared__ char smc[];
    small_gemm_body(smc, g_smeanbf, g_Bbig, g_Ppart + (size_t)blockIdx.y * NWAY * D,
                    blockIdx.x * 128, blockIdx.y, threadIdx.x);
}
__global__ void pred_kernel(const float* __restrict__ bias) {
    pred_body(bias, blockIdx.x, threadIdx.x);
}
__global__ __launch_bounds__(256) void r2_gemm(int dummy) {
    extern __shared__ char smc[];
    small_gemm_body(smc, g_Pbf, g_WbfT, g_Rpart + (size_t)blockIdx.y * NWAY * D,
                    blockIdx.x * 128, blockIdx.y, threadIdx.x);
}
__global__ void rred_kernel(int dummy) {
    int c = blockIdx.x;
    int k = blockIdx.y * 128 + threadIdx.x;
    float v = 0.f;
    #pragma unroll
    for (int js = 0; js < 8; js++)
        v += g_Rpart[(size_t)js * NWAY * D + (size_t)c * D + k];
    g_Bbig[(size_t)(512 + c) * D + k] = __float2bfloat16(v);
}

// ---------------- main GEMM: round-10 config exactly (CTA 128x64, 4-stage, grid (M/128, 9)) ----------------
#define SM_BIAS  (4 * (ASZ + BSZ) * 2)
#define SM_NORM  (SM_BIAS + 64 * 4)
#define SM_MAIN  (SM_NORM + 128 * 2 * 4)

__global__ __launch_bounds__(256, 2) void main_gemm(const float* __restrict__ bias, int M) {
    extern __shared__ char smc[];
    __nv_bfloat16* sA = (__nv_bfloat16*)smc;
    __nv_bfloat16* sB = (__nv_bfloat16*)smc + 4 * ASZ;
    float* sbias = (float*)(smc + SM_BIAS);
    float* snorm = (float*)(smc + SM_NORM);

    int tid = threadIdx.x;
    int m0 = blockIdx.x * 128;
    int nt = blockIdx.y;
    int n0 = nt * 64;
    int warp = tid >> 5, lane = tid & 31;
    int wm = warp & 3, wn = warp >> 2;
    int g = lane >> 2, t4 = lane & 3;

    if (nt < 8 && tid < 64) sbias[tid] = bias[n0 + tid];

    int aOff0 = (((wm * 32 + 0 + (lane & 15)) * SA + (lane >> 4) * 8)) * 2;
    int aOff1 = (((wm * 32 + 16 + (lane & 15)) * SA + (lane >> 4) * 8)) * 2;
    int bOff0 = (((wn * 32 + 0 + (lane & 7) + ((lane >> 4) << 3)) * SA + ((lane >> 3) & 1) * 8)) * 2;
    int bOff1 = (((wn * 32 + 16 + (lane & 7) + ((lane >> 4) << 3)) * SA + ((lane >> 3) & 1) * 8)) * 2;

    float acc[2][4][4];
    #pragma unroll
    for (int a = 0; a < 2; a++)
        #pragma unroll
        for (int b2 = 0; b2 < 4; b2++)
            #pragma unroll
            for (int c = 0; c < 4; c++) acc[a][b2][c] = 0.f;

    auto loadA = [&](int st, int kt) {
        #pragma unroll
        for (int j = 0; j < 4; j++) {
            int i = tid + j * 256, r = i >> 3, c8 = i & 7;
            int grow = m0 + r; if (grow >= M) grow = M - 1;
            cp_async16(sA + st * ASZ + r * SA + c8 * 8,
                       g_qbf + (size_t)grow * D + kt * 64 + c8 * 8);
        }
    };
    auto loadB = [&](int st, int kt) {
        #pragma unroll
        for (int j = 0; j < 2; j++) {
            int i = tid + j * 256, r = i >> 3, c8 = i & 7;
            cp_async16(sB + st * BSZ + r * SA + c8 * 8,
                       g_Bbig + (size_t)(n0 + r) * D + kt * 64 + c8 * 8);
        }
    };

    loadA(0, 0); loadB(0, 0); CP_COMMIT();
    loadA(1, 1); loadB(1, 1); CP_COMMIT();
    loadA(2, 2); loadB(2, 2); CP_COMMIT();

    uint32_t sa0 = (uint32_t)__cvta_generic_to_shared(sA);
    uint32_t sb0 = (uint32_t)__cvta_generic_to_shared(sB);

    #pragma unroll 1
    for (int kt = 0; kt < 8; kt++) {
        if (kt < 6) { CP_WAIT(2); } else if (kt == 6) { CP_WAIT(1); } else { CP_WAIT(0); }
        __syncthreads();
        if (kt + 3 < 8) { loadA((kt + 3) & 3, kt + 3); loadB((kt + 3) & 3, kt + 3); CP_COMMIT(); }
        tile_step_small(acc, sa0 + ((kt & 3) * ASZ) * 2, sb0 + ((kt & 3) * BSZ) * 2,
                        aOff0, aOff1, bOff0, bOff1);
    }

    if (nt < 8) {
        #pragma unroll
        for (int mf = 0; mf < 2; mf++) {
            float s0 = 0.f, s1 = 0.f;
            #pragma unroll
            for (int nf = 0; nf < 4; nf++) {
                int c = wn * 32 + nf * 8 + t4 * 2;
                float b0 = sbias[c], b1 = sbias[c + 1];
                float v;
                v = acc[mf][nf][0] + b0; s0 += v * v;
                v = acc[mf][nf][1] + b1; s0 += v * v;
                v = acc[mf][nf][2] + b0; s1 += v * v;
                v = acc[mf][nf][3] + b1; s1 += v * v;
            }
            s0 += __shfl_xor_sync(0xffffffffu, s0, 1);
            s0 += __shfl_xor_sync(0xffffffffu, s0, 2);
            s1 += __shfl_xor_sync(0xffffffffu, s1, 1);
            s1 += __shfl_xor_sync(0xffffffffu, s1, 2);
            if (t4 == 0) {
                int r = wm * 32 + mf * 16 + g;
                snorm[r * 2 + wn] = s0;
                snorm[(r + 8) * 2 + wn] = s1;
            }
        }
        __syncthreads();
        if (tid < 128 && m0 + tid < M)
            g_partial[(size_t)(m0 + tid) * 8 + nt] = snorm[tid * 2] + snorm[tid * 2 + 1];
    } else {
        #pragma unroll
        for (int mf = 0; mf < 2; mf++) {
            int r = wm * 32 + mf * 16 + g;
            #pragma unroll
            for (int nf = 0; nf < 4; nf++) {
                int c = wn * 32 + nf * 8 + t4 * 2;
                if (m0 + r < M) {
                    float2 o; o.x = acc[mf][nf][0]; o.y = acc[mf][nf][1];
                    *(float2*)(g_cross + (size_t)(m0 + r) * NWAY + c) = o;
                }
                if (m0 + r + 8 < M) {
                    float2 o; o.x = acc[mf][nf][2]; o.y = acc[mf][nf][3];
                    *(float2*)(g_cross + (size_t)(m0 + r + 8) * NWAY + c) = o;
                }
            }
        }
    }
}

// ---------------- combine: 128 blocks x 64 queries, vectorized ----------------
__global__ void combine_kernel(float* __restrict__ out, int M) {
    __shared__ float snq[64];
    __shared__ float spc[64];
    int tid = threadIdx.x;
    int q0 = blockIdx.x * 64;
    if (tid < 64) {
        int q = q0 + tid;
        float s = 0.f;
        if (q < M) {
            float4 a = *(const float4*)(g_partial + (size_t)q * 8);
            float4 b = *(const float4*)(g_partial + (size_t)q * 8 + 4);
            s = a.x + a.y + a.z + a.w + b.x + b.y + b.z + b.w;
        }
        snq[tid] = s;
    } else if (tid < 128) {
        spc[tid - 64] = g_pcterm[tid - 64];
    }
    __syncthreads();
    int q = q0 + (tid >> 2);
    int c0 = (tid & 3) * 16;
    if (q < M) {
        float nq = snq[tid >> 2];
        #pragma unroll
        for (int e = 0; e < 16; e += 4) {
            int c = c0 + e;
            float4 x = *(const float4*)(g_cross + (size_t)q * NWAY + c);
            float4 o;
            o.x = nq + spc[c]     - 2.f * x.x;
            o.y = nq + spc[c + 1] - 2.f * x.y;
            o.z = nq + spc[c + 2] - 2.f * x.z;
            o.w = nq + spc[c + 3] - 2.f * x.w;
            *(float4*)(out + (size_t)q * NWAY + c) = o;
        }
    }
}

// ---------------- launch ----------------
extern "C" void kernel_launch(void* const* d_in, const int* in_sizes, int n_in,
                              void* d_out, int out_size) {
    const float* support = (const float*)d_in[0];
    const float* query   = (const float*)d_in[1];
    const float* W       = (const float*)d_in[2];
    const float* bias    = (const float*)d_in[3];
    int M = in_sizes[1] / D;
    if (M > MAXQ) M = MAXQ;
    float* out = (float*)d_out;
    int qblocks = (int)(((size_t)M * D + 2047) / 2048);
    int mblocks = (M + 127) / 128;

    cudaFuncSetAttribute(main_gemm, cudaFuncAttributeMaxDynamicSharedMemorySize, SM_MAIN);

    int coopOK = 0;
    cudaDeviceGetAttribute(&coopOK, cudaDevAttrCooperativeLaunch, 0);

    prep_q_kernel<<<qblocks, 256>>>(query, M);

    bool launched = false;
    if (coopOK) {
        void* args[3] = { (void*)&W, (void*)&support, (void*)&bias };
        cudaError_t e = cudaLaunchCooperativeKernel((const void*)proto_coop,
                                                    dim3(32), dim3(256), args, SM_COOP,
                                                    (cudaStream_t)0);
        launched = (e == cudaSuccess);
    }
    if (!launched) {
        prep_w_kernel<<<256 + 64 + 64, 256>>>(W, support);
        proj_gemm<<<dim3(4, 8), 256, SM_COOP>>>(0);
        pred_kernel<<<NWAY, 256>>>(bias);
        r2_gemm<<<dim3(4, 8), 256, SM_COOP>>>(0);
        rred_kernel<<<dim3(NWAY, 4), 128>>>(0);
    }

    main_gemm<<<dim3(mblocks, 9), 256, SM_MAIN>>>(bias, M);
    combine_kernel<<<(M + 63) / 64, 256>>>(out, M);
}